// round 14
// baseline (speedup 1.0000x reference)
#include <cuda_runtime.h>
#include <cuda_bf16.h>

#define NEG_INF -1e10f

// packed f32x2 FMA: d = a*b + c (per 32-bit half), sm_103a FFMA2
#define FMA2(d, a, b, c) \
    asm("fma.rn.f32x2 %0, %1, %2, %3;" : "=l"(d) : "l"(a), "l"(b), "l"(c))
// duplicate one fp32 into both halves of a 64-bit f32x2
#define DUP2(d, s) \
    asm("mov.b64 %0, {%1, %1};" : "=l"(d) : "f"(s))

// Fully fused, warp-autonomous kernel. 128-thread blocks, reg-capped to 51
// via __launch_bounds__(128,10) -> 40 resident warps/SM (vs 32 at 64 regs).
// Each warp owns 4 consecutive nodes:
//   phase A: masked max-pool (predicated streaming, masks/ballots hoisted so
//            all 4 nodes' load streams interleave) + self-relu copy
//   phase B: 4-node GEMM vs W[128,128]; one coalesced W row read per k is
//            shared by the 4 nodes; FFMA2 packed accumulation.
// No __syncthreads -> warps drift out of phase; DRAM streaming overlaps FMA.
__global__ __launch_bounds__(128, 10)
void fused_kernel(const float* __restrict__ self_vecs,   // [N,128]
                  const float* __restrict__ neigh,       // [N,32,128]
                  const int*   __restrict__ mask,        // [N,32]
                  const float* __restrict__ W,           // [128,128]
                  float*       __restrict__ out,         // [N,256]
                  int N)
{
    // [warp][node][32] float4 = 4*4*32*16B = 8 KB
    __shared__ float4 Hs[4 * 4 * 32];

    const int tid  = threadIdx.x;
    const int lane = tid & 31;
    const int warp = tid >> 5;                    // 0..3
    const int n_base = (blockIdx.x * 4 + warp) * 4;

    // ---- hoisted masks: all 4 ballots ready before any pooling ----
    unsigned vm[4];
    #pragma unroll
    for (int r = 0; r < 4; r++) {
        const int n = n_base + r;
        int mv = 0;
        if (n < N) mv = mask[n * 32 + lane];
        vm[r] = __ballot_sync(0xffffffffu, mv > 0);
    }

    // ---------------- Phase A: pool 4 nodes ----------------
    #pragma unroll
    for (int r = 0; r < 4; r++) {
        const int n = n_base + r;                 // uniform across warp
        float4 m = make_float4(0.f, 0.f, 0.f, 0.f);
        if (n < N) {
            m = make_float4(NEG_INF, NEG_INF, NEG_INF, NEG_INF);
            const float4* np =
                reinterpret_cast<const float4*>(neigh + (size_t)n * 32 * 128) + lane;
            const unsigned v = vm[r];
            #pragma unroll
            for (int k = 0; k < 32; k++) {
                if ((v >> k) & 1u) {
                    float4 t = np[(size_t)k * 32];
                    m.x = fmaxf(m.x, t.x);
                    m.y = fmaxf(m.y, t.y);
                    m.z = fmaxf(m.z, t.z);
                    m.w = fmaxf(m.w, t.w);
                }
            }

            // self path: relu(self) -> out[:, 0:128]
            float4 s = reinterpret_cast<const float4*>(self_vecs + (size_t)n * 128)[lane];
            s.x = fmaxf(s.x, 0.f); s.y = fmaxf(s.y, 0.f);
            s.z = fmaxf(s.z, 0.f); s.w = fmaxf(s.w, 0.f);
            reinterpret_cast<float4*>(out + (size_t)n * 256)[lane] = s;
        }
        Hs[(warp * 4 + r) * 32 + lane] = m;       // conflict-free STS.128
    }
    __syncwarp();

    // ---------------- Phase B: 4-node GEMM ----------------
    // lane -> output columns [lane*4, lane*4+4); acc packed as f32x2 pairs
    unsigned long long acc[4][2];
    #pragma unroll
    for (int r = 0; r < 4; r++) { acc[r][0] = 0ull; acc[r][1] = 0ull; }

    const float4* hbase = Hs + warp * 4 * 32;
    const float*  wcol  = W + lane * 4;

    #pragma unroll 4
    for (int k4 = 0; k4 < 32; k4++) {
        // 4 k-values for each of the 4 nodes (broadcast LDS.128)
        float4 h0 = hbase[0 * 32 + k4];
        float4 h1 = hbase[1 * 32 + k4];
        float4 h2 = hbase[2 * 32 + k4];
        float4 h3 = hbase[3 * 32 + k4];

        #pragma unroll
        for (int s = 0; s < 4; s++) {
            const int k = k4 * 4 + s;
            // W[k, lane*4 .. lane*4+3]: 16B/lane, 512B coalesced per warp,
            // ONE row read serves all 4 nodes (L1-resident).
            const ulonglong2 wv =
                __ldg(reinterpret_cast<const ulonglong2*>(wcol + (size_t)k * 128));

            const float a0 = (s == 0) ? h0.x : (s == 1) ? h0.y : (s == 2) ? h0.z : h0.w;
            const float a1 = (s == 0) ? h1.x : (s == 1) ? h1.y : (s == 2) ? h1.z : h1.w;
            const float a2 = (s == 0) ? h2.x : (s == 1) ? h2.y : (s == 2) ? h2.z : h2.w;
            const float a3 = (s == 0) ? h3.x : (s == 1) ? h3.y : (s == 2) ? h3.z : h3.w;

            unsigned long long d0, d1, d2, d3;
            DUP2(d0, a0); DUP2(d1, a1); DUP2(d2, a2); DUP2(d3, a3);

            FMA2(acc[0][0], d0, wv.x, acc[0][0]);
            FMA2(acc[0][1], d0, wv.y, acc[0][1]);
            FMA2(acc[1][0], d1, wv.x, acc[1][0]);
            FMA2(acc[1][1], d1, wv.y, acc[1][1]);
            FMA2(acc[2][0], d2, wv.x, acc[2][0]);
            FMA2(acc[2][1], d2, wv.y, acc[2][1]);
            FMA2(acc[3][0], d3, wv.x, acc[3][0]);
            FMA2(acc[3][1], d3, wv.y, acc[3][1]);
        }
    }

    // unpack, relu, store neighbor half: out[n, 128 + lane*4 .. +3]
    #pragma unroll
    for (int r = 0; r < 4; r++) {
        const int n = n_base + r;
        if (n < N) {
            float c0, c1, c2, c3;
            asm("mov.b64 {%0, %1}, %2;" : "=f"(c0), "=f"(c1) : "l"(acc[r][0]));
            asm("mov.b64 {%0, %1}, %2;" : "=f"(c2), "=f"(c3) : "l"(acc[r][1]));
            float4 cv;
            cv.x = fmaxf(c0, 0.f); cv.y = fmaxf(c1, 0.f);
            cv.z = fmaxf(c2, 0.f); cv.w = fmaxf(c3, 0.f);
            reinterpret_cast<float4*>(out + (size_t)n * 256 + 128)[lane] = cv;
        }
    }
}

extern "C" void kernel_launch(void* const* d_in, const int* in_sizes, int n_in,
                              void* d_out, int out_size)
{
    const float* self_vecs = (const float*)d_in[0];   // [N,128]
    const float* neigh     = (const float*)d_in[1];   // [N,32,128]
    const int*   mask      = (const int*)  d_in[2];   // [N,32]
    const float* W         = (const float*)d_in[3];   // [128,128]
    float* out = (float*)d_out;                        // [N,256]

    const int N = in_sizes[0] / 128;

    // 16 nodes per 128-thread block (4 nodes per warp)
    const int grid = (N + 15) / 16;
    fused_kernel<<<grid, 128>>>(self_vecs, neigh, mask, W, out, N);
}

// round 16
// speedup vs baseline: 1.1622x; 1.1622x over previous
#include <cuda_runtime.h>
#include <cuda_bf16.h>

#define NEG_INF -1e10f

// packed f32x2 FMA: d = a*b + c (per 32-bit half), sm_103a FFMA2
#define FMA2(d, a, b, c) \
    asm("fma.rn.f32x2 %0, %1, %2, %3;" : "=l"(d) : "l"(a), "l"(b), "l"(c))
// duplicate one fp32 into both halves of a 64-bit f32x2
#define DUP2(d, s) \
    asm("mov.b64 %0, {%1, %1};" : "=l"(d) : "f"(s))

// 512-byte NEG_INF row: dummy target for invalid-neighbor loads.
// Static device initializer (no runtime allocation). L1-resident after first
// touch, so invalid slots cost zero DRAM traffic, and fmax(m, NEG_INF) == m.
#define NI4  NEG_INF, NEG_INF, NEG_INF, NEG_INF
#define NI16 NI4, NI4, NI4, NI4
#define NI64 NI16, NI16, NI16, NI16
__device__ const float g_neginf[128] = { NI64, NI64 };

// Fully fused, warp-autonomous kernel (R10 shape + branchless pooling).
// Each warp owns 4 consecutive nodes:
//   phase A: max-pool with BRANCHLESS masked loads — the load address is
//            selected (selp.b64) between the real row and the NEG_INF dummy,
//            so all 32 loads per node are straight-line and ptxas batches
//            them to the register limit (high MLP). No BSSY/BSYNC.
//   phase B: 4-node GEMM vs W[128,128]; one coalesced W row read per k is
//            shared by the 4 nodes; FFMA2 packed accumulation.
// No __syncthreads -> warps drift out of phase; DRAM streaming overlaps FMA.
__global__ __launch_bounds__(256, 4)
void fused_kernel(const float* __restrict__ self_vecs,   // [N,128]
                  const float* __restrict__ neigh,       // [N,32,128]
                  const int*   __restrict__ mask,        // [N,32]
                  const float* __restrict__ W,           // [128,128]
                  float*       __restrict__ out,         // [N,256]
                  int N)
{
    // [warp][node][32] float4 = 8*4*32*16B = 16 KB
    __shared__ float4 Hs[8 * 4 * 32];

    const int tid  = threadIdx.x;
    const int lane = tid & 31;
    const int warp = tid >> 5;                    // 0..7
    const int n_base = (blockIdx.x * 8 + warp) * 4;

    // ---- hoisted masks: all 4 ballots ready before any pooling ----
    unsigned vm[4];
    #pragma unroll
    for (int r = 0; r < 4; r++) {
        const int n = n_base + r;
        int mv = 0;
        if (n < N) mv = mask[n * 32 + lane];
        vm[r] = __ballot_sync(0xffffffffu, mv > 0);
    }

    const float4* ni = reinterpret_cast<const float4*>(g_neginf) + lane;

    // ---------------- Phase A: pool 4 nodes (branchless) ----------------
    #pragma unroll
    for (int r = 0; r < 4; r++) {
        const int n = n_base + r;                 // uniform across warp
        float4 m = make_float4(0.f, 0.f, 0.f, 0.f);
        if (n < N) {
            m = make_float4(NEG_INF, NEG_INF, NEG_INF, NEG_INF);
            const float4* np =
                reinterpret_cast<const float4*>(neigh + (size_t)n * 32 * 128) + lane;
            const unsigned v = vm[r];
            #pragma unroll
            for (int k = 0; k < 32; k++) {
                // branchless address select: real row if valid, NEG_INF row if not
                const float4* a = ((v >> k) & 1u) ? (np + (size_t)k * 32) : ni;
                const float4 t = __ldg(a);
                m.x = fmaxf(m.x, t.x);
                m.y = fmaxf(m.y, t.y);
                m.z = fmaxf(m.z, t.z);
                m.w = fmaxf(m.w, t.w);
            }

            // self path: relu(self) -> out[:, 0:128]
            float4 s = reinterpret_cast<const float4*>(self_vecs + (size_t)n * 128)[lane];
            s.x = fmaxf(s.x, 0.f); s.y = fmaxf(s.y, 0.f);
            s.z = fmaxf(s.z, 0.f); s.w = fmaxf(s.w, 0.f);
            reinterpret_cast<float4*>(out + (size_t)n * 256)[lane] = s;
        }
        Hs[(warp * 4 + r) * 32 + lane] = m;       // conflict-free STS.128
    }
    __syncwarp();

    // ---------------- Phase B: 4-node GEMM ----------------
    // lane -> output columns [lane*4, lane*4+4); acc packed as f32x2 pairs
    unsigned long long acc[4][2];
    #pragma unroll
    for (int r = 0; r < 4; r++) { acc[r][0] = 0ull; acc[r][1] = 0ull; }

    const float4* hbase = Hs + warp * 4 * 32;
    const float*  wcol  = W + lane * 4;

    #pragma unroll 4
    for (int k4 = 0; k4 < 32; k4++) {
        // 4 k-values for each of the 4 nodes (broadcast LDS.128)
        float4 h0 = hbase[0 * 32 + k4];
        float4 h1 = hbase[1 * 32 + k4];
        float4 h2 = hbase[2 * 32 + k4];
        float4 h3 = hbase[3 * 32 + k4];

        #pragma unroll
        for (int s = 0; s < 4; s++) {
            const int k = k4 * 4 + s;
            // W[k, lane*4 .. lane*4+3]: 16B/lane, 512B coalesced per warp,
            // ONE row read serves all 4 nodes (L1-resident).
            const ulonglong2 wv =
                __ldg(reinterpret_cast<const ulonglong2*>(wcol + (size_t)k * 128));

            const float a0 = (s == 0) ? h0.x : (s == 1) ? h0.y : (s == 2) ? h0.z : h0.w;
            const float a1 = (s == 0) ? h1.x : (s == 1) ? h1.y : (s == 2) ? h1.z : h1.w;
            const float a2 = (s == 0) ? h2.x : (s == 1) ? h2.y : (s == 2) ? h2.z : h2.w;
            const float a3 = (s == 0) ? h3.x : (s == 1) ? h3.y : (s == 2) ? h3.z : h3.w;

            unsigned long long d0, d1, d2, d3;
            DUP2(d0, a0); DUP2(d1, a1); DUP2(d2, a2); DUP2(d3, a3);

            FMA2(acc[0][0], d0, wv.x, acc[0][0]);
            FMA2(acc[0][1], d0, wv.y, acc[0][1]);
            FMA2(acc[1][0], d1, wv.x, acc[1][0]);
            FMA2(acc[1][1], d1, wv.y, acc[1][1]);
            FMA2(acc[2][0], d2, wv.x, acc[2][0]);
            FMA2(acc[2][1], d2, wv.y, acc[2][1]);
            FMA2(acc[3][0], d3, wv.x, acc[3][0]);
            FMA2(acc[3][1], d3, wv.y, acc[3][1]);
        }
    }

    // unpack, relu, store neighbor half: out[n, 128 + lane*4 .. +3]
    #pragma unroll
    for (int r = 0; r < 4; r++) {
        const int n = n_base + r;
        if (n < N) {
            float c0, c1, c2, c3;
            asm("mov.b64 {%0, %1}, %2;" : "=f"(c0), "=f"(c1) : "l"(acc[r][0]));
            asm("mov.b64 {%0, %1}, %2;" : "=f"(c2), "=f"(c3) : "l"(acc[r][1]));
            float4 cv;
            cv.x = fmaxf(c0, 0.f); cv.y = fmaxf(c1, 0.f);
            cv.z = fmaxf(c2, 0.f); cv.w = fmaxf(c3, 0.f);
            reinterpret_cast<float4*>(out + (size_t)n * 256 + 128)[lane] = cv;
        }
    }
}

extern "C" void kernel_launch(void* const* d_in, const int* in_sizes, int n_in,
                              void* d_out, int out_size)
{
    const float* self_vecs = (const float*)d_in[0];   // [N,128]
    const float* neigh     = (const float*)d_in[1];   // [N,32,128]
    const int*   mask      = (const int*)  d_in[2];   // [N,32]
    const float* W         = (const float*)d_in[3];   // [128,128]
    float* out = (float*)d_out;                        // [N,256]

    const int N = in_sizes[0] / 128;

    // 32 nodes per 256-thread block (4 nodes per warp)
    const int grid = (N + 31) / 32;
    fused_kernel<<<grid, 256>>>(self_vecs, neigh, mask, W, out, N);
}